// round 13
// baseline (speedup 1.0000x reference)
#include <cuda_runtime.h>

// Persistent scratch (no allocations allowed). g_sum starts 0; finish resets
// it after reading, so every graph replay sees a clean state.
__device__ float g_sum = 0.f;

__device__ __forceinline__ float leaky(float v) {
    return v >= 0.f ? v : 0.2f * v;
}

// Cold path: full edge contribution. __noinline__ keeps the hot scan loop's
// register allocation and instruction footprint lean; this executes on only
// ~E/N (~32) threads chip-wide.
__device__ __noinline__ void contribute(int i, int dst,
                                        const float* __restrict__ h,
                                        const float* __restrict__ W,
                                        const float* __restrict__ bptr,
                                        int D) {
    const float4* __restrict__ ra = (const float4*)(h + (size_t)i * D);
    const float4* __restrict__ wa = (const float4*)W;
    const float4* __restrict__ rb = (const float4*)(h + (size_t)dst * D);
    const float4* __restrict__ wb = (const float4*)(W + D);
    float sa = 0.f, sb = 0.f;
    int n4 = D >> 2;
    #pragma unroll 8
    for (int k = 0; k < n4; k++) {
        float4 x = ra[k], y = wa[k];
        sa += x.x * y.x + x.y * y.y + x.z * y.z + x.w * y.w;
        float4 u = rb[k], v = wb[k];
        sb += u.x * v.x + u.y * v.y + u.z * v.z + u.w * v.w;
    }
    atomicAdd(&g_sum, leaky(sa + sb + __ldg(bptr)));
}

// ---------------------------------------------------------------------------
// Kernel 1: lean scan (2 x int4 = 4 edges per thread, coalesced). Matching
// threads take the cold contribute() path.
// ---------------------------------------------------------------------------
__global__ void __launch_bounds__(256)
gat_scan(const int4* __restrict__ g4, unsigned nPairs, int rem,
         const int2* __restrict__ gall,
         const float* __restrict__ h, const float* __restrict__ W,
         const float* __restrict__ bptr, const int* __restrict__ ip, int D) {
    const unsigned t = threadIdx.x;
    const unsigned base = blockIdx.x * 512u + t;
    const int i = __ldg(ip);

    int4 p0, p1;
    const bool v0 = base < nPairs;
    const bool v1 = (base + 256u) < nPairs;
    if (v0) p0 = __ldg(&g4[base]);
    if (v1) p1 = __ldg(&g4[base + 256u]);

    if (v0) {
        if (__builtin_expect(p0.x == i, 0)) contribute(i, p0.y, h, W, bptr, D);
        if (__builtin_expect(p0.z == i, 0)) contribute(i, p0.w, h, W, bptr, D);
    }
    if (v1) {
        if (__builtin_expect(p1.x == i, 0)) contribute(i, p1.y, h, W, bptr, D);
        if (__builtin_expect(p1.z == i, 0)) contribute(i, p1.w, h, W, bptr, D);
    }
    if (rem && blockIdx.x == 0 && t == 0) {
        int2 p = __ldg(&gall[(size_t)2 * nPairs]);   // trailing odd edge
        if (p.x == i) contribute(i, p.y, h, W, bptr, D);
    }
}

// ---------------------------------------------------------------------------
// Kernel 2: minimal finish. 64 threads: warp 0 -> s_src[i], warp 1 -> s_dst[j],
// then out[0] = leaky(ssrc + sdstj + b) / g_sum; reset g_sum.
// ---------------------------------------------------------------------------
__global__ void __launch_bounds__(64)
gat_finish(const float* __restrict__ h, const float* __restrict__ W,
           const float* __restrict__ bptr,
           const int* __restrict__ ip, const int* __restrict__ jp,
           int D, float* __restrict__ out) {
    const int t = threadIdx.x;
    const int lane = t & 31;
    const int w = t >> 5;

    __shared__ float sh[2];

    const int row  = (w == 0) ? __ldg(ip) : __ldg(jp);
    const float* wvec = (w == 0) ? W : (W + D);

    // warp-collective dot: lane reads float4 at 4*lane (D=128 exactly covered)
    float s = 0.f;
    for (int k = 4 * lane; k < D; k += 128) {
        float4 a = *(const float4*)(h + (size_t)row * D + k);
        float4 b = *(const float4*)(wvec + k);
        s += a.x * b.x + a.y * b.y + a.z * b.z + a.w * b.w;
    }
    #pragma unroll
    for (int off = 16; off > 0; off >>= 1)
        s += __shfl_down_sync(0xffffffffu, s, off);
    if (lane == 0) sh[w] = s;
    __syncthreads();

    if (t == 0) {
        float e = leaky(sh[0] + sh[1] + __ldg(bptr));
        out[0] = e / g_sum;
        g_sum = 0.f;   // reset for next graph replay
    }
}

extern "C" void kernel_launch(void* const* d_in, const int* in_sizes, int n_in,
                              void* d_out, int out_size) {
    // metadata order: g (E*2 int32), h (N*D f32), i, j, W (2D f32), b (1 f32)
    const int*   g  = (const int*)d_in[0];
    const float* h  = (const float*)d_in[1];
    const int*   ip = (const int*)d_in[2];
    const int*   jp = (const int*)d_in[3];
    const float* W  = (const float*)d_in[4];
    const float* b  = (const float*)d_in[5];
    float* out = (float*)d_out;

    long long E = (long long)in_sizes[0] / 2;
    int D = in_sizes[4] / 2;

    unsigned nPairs = (unsigned)(E / 2);   // int4 units (2 edges each)
    int rem = (int)(E & 1);

    unsigned nBlocks = (nPairs + 511u) / 512u;
    if (nBlocks < 1u) nBlocks = 1u;

    gat_scan<<<nBlocks, 256>>>((const int4*)g, nPairs, rem, (const int2*)g,
                               h, W, b, ip, D);
    gat_finish<<<1, 64>>>(h, W, b, ip, jp, D, out);
}